// round 16
// baseline (speedup 1.0000x reference)
#include <cuda_runtime.h>
#include <cuda_bf16.h>

#define NB 16384
#define NF 26
#define FIELD_DIM 100000
#define WARPS_PER_CTA 8

typedef unsigned long long u64;

// L2-policy-hinted loads: keep gathered table lines resident (evict_last).
__device__ __forceinline__ float2 ldg_pol2(const float2* p, u64 pol) {
    float2 v;
    asm("ld.global.nc.L2::cache_hint.v2.f32 {%0,%1}, [%2], %3;"
        : "=f"(v.x), "=f"(v.y) : "l"(p), "l"(pol));
    return v;
}
__device__ __forceinline__ float ldg_pol1(const float* p, u64 pol) {
    float v;
    asm("ld.global.nc.L2::cache_hint.f32 %0, [%1], %2;"
        : "=f"(v) : "l"(p), "l"(pol));
    return v;
}

__global__ __launch_bounds__(256) void mixdim_embbag_kernel(
    const int* __restrict__ x,
    const float* __restrict__ t0,
    const float* __restrict__ t1,
    const float* __restrict__ t2,
    const float* __restrict__ W1,
    const float* __restrict__ b1,
    const float* __restrict__ W2,
    const float* __restrict__ b2,
    float* __restrict__ out)
{
    __shared__ __align__(16) float sW1[64 * 36];
    __shared__ __align__(16) float sW2[64 * 20];
    __shared__ __align__(16) float sh0[WARPS_PER_CTA][64];
    __shared__ __align__(16) float sh1[WARPS_PER_CTA][32];
    __shared__ __align__(16) float sh2[WARPS_PER_CTA][16];

    const int tid = threadIdx.x;
    const int w   = tid >> 5;
    const int l   = tid & 31;
    const int row = blockIdx.x * WARPS_PER_CTA + w;

    u64 pol_last, pol_first;
    asm("createpolicy.fractional.L2::evict_last.b64 %0, 1.0;"  : "=l"(pol_last));
    asm("createpolicy.fractional.L2::evict_first.b64 %0, 1.0;" : "=l"(pol_first));

    // ---- Stage W1/W2 into shared (coalesced) ----
    #pragma unroll
    for (int i = 0; i < 8; ++i) {
        int idx = tid + 256 * i;
        sW1[(idx >> 5) * 36 + (idx & 31)] = W1[idx];
    }
    #pragma unroll
    for (int i = 0; i < 4; ++i) {
        int idx = tid + 256 * i;
        sW2[(idx >> 4) * 20 + (idx & 15)] = W2[idx];
    }
    const int d  = tid & 63;
    const int rb = tid >> 6;
    const float bd = 8.f * __ldg(&b1[d]) + 10.f * __ldg(&b2[d]);  // b==0 in dataset; kept exact

    // ---- Gather phase: one warp per row; x read is streaming (evict_first) ----
    int xi = 0;
    if (l < NF) {
        int t;
        asm("ld.global.nc.L2::cache_hint.s32 %0, [%1], %2;"
            : "=r"(t) : "l"(x + row * NF + l), "l"(pol_first));
        xi = t;
    }

    int i0[8], i1[8], i2[5];
    #pragma unroll
    for (int f = 0; f < 8; ++f)
        i0[f] = __shfl_sync(0xffffffffu, xi, f) + f * FIELD_DIM;
    #pragma unroll
    for (int f = 0; f < 8; ++f)
        i1[f] = __shfl_sync(0xffffffffu, xi, 8 + f) + f * FIELD_DIM;
    const int half = l >> 4;
    #pragma unroll
    for (int p = 0; p < 5; ++p) {
        int fld = 2 * p + half;
        i2[p] = __shfl_sync(0xffffffffu, xi, 16 + fld) + fld * FIELD_DIM;
    }

    float2 v0[8];
    float  v1[8];
    float  v2[5];
    const float2* t0v = reinterpret_cast<const float2*>(t0);
    const int l16 = l & 15;
    #pragma unroll
    for (int f = 0; f < 8; ++f) v0[f] = ldg_pol2(&t0v[i0[f] * 32 + l], pol_last);
    #pragma unroll
    for (int f = 0; f < 8; ++f) v1[f] = ldg_pol1(&t1[i1[f] * 32 + l], pol_last);
    #pragma unroll
    for (int p = 0; p < 5; ++p) v2[p] = ldg_pol1(&t2[i2[p] * 16 + l16], pol_last);

    float2 acc = make_float2(0.f, 0.f);
    #pragma unroll
    for (int f = 0; f < 8; ++f) { acc.x += v0[f].x; acc.y += v0[f].y; }
    float s1 = 0.f;
    #pragma unroll
    for (int f = 0; f < 8; ++f) s1 += v1[f];
    float s2 = 0.f;
    #pragma unroll
    for (int p = 0; p < 5; ++p) s2 += v2[p];
    s2 += __shfl_xor_sync(0xffffffffu, s2, 16);

    reinterpret_cast<float2*>(&sh0[w][0])[l] = acc;
    sh1[w][l] = s1;
    if (l < 16) sh2[w][l] = s2;
    __syncthreads();

    // ---- Projection + direct store (evict_first on out) ----
    const float4* w1v = reinterpret_cast<const float4*>(&sW1[d * 36]);
    const float4* w2v = reinterpret_cast<const float4*>(&sW2[d * 20]);
    #pragma unroll
    for (int rr = 0; rr < 2; ++rr) {
        const int r = rb + 4 * rr;
        const float4* s1v = reinterpret_cast<const float4*>(&sh1[r][0]);
        const float4* s2v = reinterpret_cast<const float4*>(&sh2[r][0]);
        float p = sh0[r][d] + bd;
        #pragma unroll
        for (int j = 0; j < 8; ++j) {
            float4 wv = w1v[j], sv = s1v[j];
            p += wv.x * sv.x + wv.y * sv.y + wv.z * sv.z + wv.w * sv.w;
        }
        #pragma unroll
        for (int j = 0; j < 4; ++j) {
            float4 wv = w2v[j], sv = s2v[j];
            p += wv.x * sv.x + wv.y * sv.y + wv.z * sv.z + wv.w * sv.w;
        }
        asm volatile("st.global.L2::cache_hint.f32 [%0], %1, %2;"
                     :: "l"(out + (blockIdx.x * WARPS_PER_CTA + r) * 64 + d),
                        "f"(p), "l"(pol_first));
    }
}

extern "C" void kernel_launch(void* const* d_in, const int* in_sizes, int n_in,
                              void* d_out, int out_size) {
    const int*   x  = (const int*)  d_in[0];
    const float* t0 = (const float*)d_in[1];
    const float* t1 = (const float*)d_in[2];
    const float* t2 = (const float*)d_in[3];
    const float* W1 = (const float*)d_in[4];
    const float* b1 = (const float*)d_in[5];
    const float* W2 = (const float*)d_in[6];
    const float* b2 = (const float*)d_in[7];
    float* out = (float*)d_out;

    dim3 grid(NB / WARPS_PER_CTA);   // 2048 CTAs, one 8-row group each
    dim3 block(32 * WARPS_PER_CTA);
    mixdim_embbag_kernel<<<grid, block>>>(x, t0, t1, t2, W1, b1, W2, b2, out);
}